// round 15
// baseline (speedup 1.0000x reference)
#include <cuda_runtime.h>
#include <cuda_bf16.h>
#include <cstdint>

// Fixed shapes: x=(2,64,8,32,32); HEAD=4, HEAD_DIM=16; H2=64, W2=128; L=8192
#define LPIX 8192
#define NH 8   // b*HEAD

typedef unsigned long long u64;

// Scratch (device globals) — all fp32 float4 planes [n*4+c4][l]
__device__ float4 g_QS4[NH * 4 * LPIX];   // q*0.25
__device__ float4 g_KM4[NH * 4 * LPIX];   // k - pe
__device__ float4 g_VV4[NH * 4 * LPIX];   // v
__device__ float  g_QPEC[NH * LPIX];      // sum_c q_s[c]*pe[c]
__device__ __align__(16) float g_F144[2 * 144 * LPIX]; // planar [b][ch144][l]
__device__ float g_Weff[144 * 64];        // wfc-folded qkv weights
__device__ float g_beff[144];

// ---- packed f32x2 helpers (sm_103a) ---------------------------------------
__device__ __forceinline__ void ffma2(u64 &d, u64 a, u64 b) {
    asm("fma.rn.f32x2 %0, %1, %2, %0;" : "+l"(d) : "l"(a), "l"(b));
}
__device__ __forceinline__ u64 pack2(float lo, float hi) {
    u64 r; asm("mov.b64 %0, {%1, %2};" : "=l"(r) : "f"(lo), "f"(hi)); return r;
}
__device__ __forceinline__ float2 unpack2(u64 v) {
    float lo, hi; asm("mov.b64 {%0, %1}, %2;" : "=f"(lo), "=f"(hi) : "l"(v)); return make_float2(lo, hi);
}

// ---------------------------------------------------------------------------
// K0: fold wfc into the qkv weights.
//   Weff[j*16+hd][cin] = sum_{t,h} wfc[j][t*4+h] * Wt[(h*16+hd)*64+cin]
//   beff[j*16+hd]      = sum_{t,h} wfc[j][t*4+h] * bt[h*16+hd]
// ---------------------------------------------------------------------------
__global__ __launch_bounds__(128) void k0_weff(
    const float* __restrict__ w1, const float* __restrict__ b1,
    const float* __restrict__ w2, const float* __restrict__ b2,
    const float* __restrict__ w3, const float* __restrict__ b3,
    const float* __restrict__ wfc)
{
    int idx = blockIdx.x * 128 + threadIdx.x;
    if (idx < 9216) {
        int j = idx >> 10;
        int r = idx & 1023;
        int hd = r >> 6, cin = r & 63;
        float s = 0.0f;
#pragma unroll
        for (int h = 0; h < 4; h++) {
            int row = (h * 16 + hd) * 64 + cin;
            s += wfc[j*12 + h]     * w1[row];
            s += wfc[j*12 + 4 + h] * w2[row];
            s += wfc[j*12 + 8 + h] * w3[row];
        }
        g_Weff[(j * 16 + hd) * 64 + cin] = s;
    } else if (idx < 9360) {
        int e = idx - 9216;
        int j = e >> 4, hd = e & 15;
        float s = 0.0f;
#pragma unroll
        for (int h = 0; h < 4; h++) {
            int row = h * 16 + hd;
            s += wfc[j*12 + h]     * b1[row];
            s += wfc[j*12 + 4 + h] * b2[row];
            s += wfc[j*12 + 8 + h] * b3[row];
        }
        g_beff[j * 16 + hd] = s;
    }
}

// ---------------------------------------------------------------------------
// FAT1: 21 role variants, all reading only x.
//   blockIdx.y < 12 : qkv roles (head = y/3, type = y%3) — q/k/v + PE fold
//   blockIdx.y >= 12: F144 roles (j = y-12) — F144[j*16+c] = Weff@x + beff
// 2-pixel blocking, LDS.64 weight broadcasts interleaved with FFMA2.
// ---------------------------------------------------------------------------
__global__ __launch_bounds__(128) void fat1(
    const float* __restrict__ x,
    const float* __restrict__ w1, const float* __restrict__ b1,
    const float* __restrict__ w2, const float* __restrict__ b2,
    const float* __restrict__ w3, const float* __restrict__ b3,
    const float* __restrict__ wp, const float* __restrict__ bp)
{
    __shared__ float sw[64][16];
    __shared__ float sb[16], swp[48], sbp[16];
    const int tid = threadIdx.x;
    const int ht = blockIdx.y;
    const int b = blockIdx.z;
    const bool is_f = (ht >= 12);
    const int head = is_f ? 0 : ht / 3;
    const int type = is_f ? 0 : ht - head * 3;
    const int j = is_f ? (ht - 12) : 0;

    if (is_f) {
        for (int i = tid; i < 1024; i += 128) {
            int c = i & 15, cin = i >> 4;
            sw[cin][c] = g_Weff[(j * 16 + c) * 64 + cin];
        }
        if (tid < 16) sb[tid] = g_beff[j * 16 + tid];
    } else {
        const float* wm = (type == 0) ? w1 : (type == 1) ? w2 : w3;
        const float* bm = (type == 0) ? b1 : (type == 1) ? b2 : b3;
        for (int i = tid; i < 1024; i += 128) {
            int c = i & 15, cin = i >> 4;
            sw[cin][c] = wm[(head * 16 + c) * 64 + cin];
        }
        if (tid < 16) sb[tid] = bm[head * 16 + tid];
    }
    if (tid < 48) swp[tid] = wp[tid];
    if (tid < 16) sbp[tid] = bp[tid];
    __syncthreads();

    const int l0 = blockIdx.x * 256 + tid * 2;

    u64 acc[2][8];
#pragma unroll
    for (int jj = 0; jj < 8; jj++) {
        u64 bj = pack2(sb[2*jj], sb[2*jj+1]);
        acc[0][jj] = bj;
        acc[1][jj] = bj;
    }

    const float* xp = x + (size_t)b * 64 * LPIX + l0;
#pragma unroll 4
    for (int cin = 0; cin < 64; cin++) {
        float2 xv = *reinterpret_cast<const float2*>(xp + (size_t)cin * LPIX);
        u64 xa = pack2(xv.x, xv.x);
        u64 xb = pack2(xv.y, xv.y);
        const u64* w2p = reinterpret_cast<const u64*>(sw[cin]);
#pragma unroll
        for (int jj = 0; jj < 8; jj++) {
            u64 wj = w2p[jj];
            ffma2(acc[0][jj], xa, wj);
            ffma2(acc[1][jj], xb, wj);
        }
    }

#pragma unroll
    for (int p = 0; p < 2; p++) {
        const int l = l0 + p;
        float a[16];
#pragma unroll
        for (int jj = 0; jj < 8; jj++) {
            float2 t = unpack2(acc[p][jj]); a[2*jj] = t.x; a[2*jj+1] = t.y;
        }

        if (is_f) {
#pragma unroll
            for (int c = 0; c < 16; c++)
                g_F144[((size_t)(b * 144 + j * 16 + c)) * LPIX + l] = a[c];
            continue;
        }

        int di = l >> 10, wi = (l >> 5) & 31, hi = l & 31;
        float ldv = di * (2.0f/7.0f)  - 1.0f;
        float lwv = wi * (2.0f/31.0f) - 1.0f;
        float lhv = hi * (2.0f/31.0f) - 1.0f;
        float pe[16];
#pragma unroll
        for (int c = 0; c < 16; c++)
            pe[c] = swp[c*3] * ldv + swp[c*3+1] * lwv + swp[c*3+2] * lhv + sbp[c];

        const int n = b * 4 + head;
        if (type == 0) {
            float qpec = 0.0f;
#pragma unroll
            for (int c = 0; c < 16; c++) { a[c] *= 0.25f; qpec += a[c] * pe[c]; }
#pragma unroll
            for (int c4 = 0; c4 < 4; c4++)
                g_QS4[((size_t)(n * 4 + c4)) * LPIX + l] =
                    make_float4(a[c4*4], a[c4*4+1], a[c4*4+2], a[c4*4+3]);
            g_QPEC[n * LPIX + l] = qpec;
        } else if (type == 1) {
#pragma unroll
            for (int c = 0; c < 16; c++) a[c] -= pe[c];
#pragma unroll
            for (int c4 = 0; c4 < 4; c4++)
                g_KM4[((size_t)(n * 4 + c4)) * LPIX + l] =
                    make_float4(a[c4*4], a[c4*4+1], a[c4*4+2], a[c4*4+3]);
        } else {
#pragma unroll
            for (int c4 = 0; c4 < 4; c4++)
                g_VV4[((size_t)(n * 4 + c4)) * LPIX + l] =
                    make_float4(a[c4*4], a[c4*4+1], a[c4*4+2], a[c4*4+3]);
        }
    }
}

// ---------------------------------------------------------------------------
// K4: grouped 3x3 conv from smem-staged F144 rows; 4 pixels per thread.
// ---------------------------------------------------------------------------
__global__ __launch_bounds__(256) void k4_conv(
    const float* __restrict__ wdep, const float* __restrict__ bdep,
    const float* __restrict__ rate2,
    float* __restrict__ out)
{
    extern __shared__ float sm[];                 // 27 rows x 1024 floats
    __shared__ u64 w01[81], w23[81];
    __shared__ float sb[4];
    __shared__ float sr2;
    const int tid = threadIdx.x;
    const int dd = blockIdx.x, go = blockIdx.y, b = blockIdx.z;

    if (tid < 81) {
        w01[tid] = pack2(wdep[(go*4+0)*81 + tid], wdep[(go*4+1)*81 + tid]);
        w23[tid] = pack2(wdep[(go*4+2)*81 + tid], wdep[(go*4+3)*81 + tid]);
    }
    if (tid < 4) sb[tid] = bdep[go*4+tid];
    if (tid == 0) sr2 = rate2[0];

    for (int i = tid; i < 27 * 256; i += 256) {
        int row = i >> 8, px4 = (i & 255) << 2;
        int ci = row / 3, r = row - ci * 3;
        int ddn = dd + r - 1;
        float4 val = make_float4(0.f, 0.f, 0.f, 0.f);
        if ((unsigned)ddn < 8u)
            val = *reinterpret_cast<const float4*>(
                g_F144 + ((size_t)(b*144 + go*9 + ci)) * LPIX + ddn * 1024 + px4);
        *reinterpret_cast<float4*>(&sm[row * 1024 + px4]) = val;
    }
    __syncthreads();

    const int p0 = tid * 4;
    u64 a01[4], a23[4];
#pragma unroll
    for (int p = 0; p < 4; p++) {
        a01[p] = pack2(sb[0], sb[1]);
        a23[p] = pack2(sb[2], sb[3]);
    }

#pragma unroll
    for (int ci = 0; ci < 9; ci++) {
#pragma unroll
        for (int r = 0; r < 3; r++) {
            const float* row = sm + (ci * 3 + r) * 1024;
            float v[6];
            float4 mid = *reinterpret_cast<const float4*>(row + p0);
            v[1] = mid.x; v[2] = mid.y; v[3] = mid.z; v[4] = mid.w;
            v[0] = (p0 > 0)        ? row[p0 - 1] : 0.0f;
            v[5] = (p0 + 4 < 1024) ? row[p0 + 4] : 0.0f;
            int t = ci * 9 + r * 3;
#pragma unroll
            for (int kw = 0; kw < 3; kw++) {
                u64 wa = w01[t + kw], wb = w23[t + kw];
#pragma unroll
                for (int p = 0; p < 4; p++) {
                    u64 vm = pack2(v[p + kw], v[p + kw]);
                    ffma2(a01[p], vm, wa);
                    ffma2(a23[p], vm, wb);
                }
            }
        }
    }

    size_t ob = ((size_t)(b * 64 + go * 4)) * LPIX + dd * 1024 + p0;
    float o0[4], o1[4], o2v[4], o3[4];
#pragma unroll
    for (int p = 0; p < 4; p++) {
        float2 r01 = unpack2(a01[p]), r23 = unpack2(a23[p]);
        o0[p] = sr2 * r01.x; o1[p] = sr2 * r01.y;
        o2v[p] = sr2 * r23.x; o3[p] = sr2 * r23.y;
    }
    *reinterpret_cast<float4*>(out + ob)            = make_float4(o0[0], o0[1], o0[2], o0[3]);
    *reinterpret_cast<float4*>(out + ob + LPIX)     = make_float4(o1[0], o1[1], o1[2], o1[3]);
    *reinterpret_cast<float4*>(out + ob + 2*LPIX)   = make_float4(o2v[0], o2v[1], o2v[2], o2v[3]);
    *reinterpret_cast<float4*>(out + ob + 3*LPIX)   = make_float4(o3[0], o3[1], o3[2], o3[3]);
}

// ---------------------------------------------------------------------------
// K3: 7x7 window attention, fused no-max softmax, fp32, native u64 loads,
// vertical 2-pixel blocking + 2-way row split; 2 blocks/SM.
// Accumulates rate1*att into out (after k4 wrote rate2*conv).
// ---------------------------------------------------------------------------
__global__ __launch_bounds__(256, 2) void k3_att(
    const float* __restrict__ rate1, float* __restrict__ out)
{
    __shared__ float s_sum[2][128];
    __shared__ float s_o[2][128][17];

    const int n = blockIdx.y;
    const int tid = threadIdx.x;
    const int half = tid >> 7;
    const int t = tid & 127;           // x coordinate
    const int y0 = blockIdx.x << 1;
    const int l0 = (y0 << 7) + t;
    const int l1 = l0 + 128;

    const ulonglong2* __restrict__ kp =
        reinterpret_cast<const ulonglong2*>(g_KM4 + (size_t)(n * 4) * LPIX);
    const ulonglong2* __restrict__ vp =
        reinterpret_cast<const ulonglong2*>(g_VV4 + (size_t)(n * 4) * LPIX);
    const ulonglong2* __restrict__ qp =
        reinterpret_cast<const ulonglong2*>(g_QS4 + (size_t)(n * 4) * LPIX);

    u64 q0[8], q1[8];
#pragma unroll
    for (int c4 = 0; c4 < 4; c4++) {
        ulonglong2 qa = qp[(size_t)c4 * LPIX + l0];
        q0[c4*2] = qa.x; q0[c4*2+1] = qa.y;
        ulonglong2 qb = qp[(size_t)c4 * LPIX + l1];
        q1[c4*2] = qb.x; q1[c4*2+1] = qb.y;
    }
    const float qpec0 = g_QPEC[n * LPIX + l0];
    const float qpec1 = g_QPEC[n * LPIX + l1];

    int xs[7];
#pragma unroll
    for (int jj = 0; jj < 7; jj++) {
        int xm = t + jj - 3;
        xs[jj] = xm < 0 ? -xm : (xm > 127 ? 254 - xm : xm);
    }

    u64 o0[8], o1[8];
#pragma unroll
    for (int c = 0; c < 8; c++) { o0[c] = 0ULL; o1[c] = 0ULL; }
    float sum0 = 0.0f, sum1 = 0.0f;

#pragma unroll 1
    for (int r = 0; r < 4; r++) {
        const int rr = half * 4 + r;             // union row 0..7
        int yy = y0 + rr - 3;
        yy = yy < 0 ? -yy : (yy > 63 ? 126 - yy : yy);
        const int rb = yy << 7;
        const float m0 = (rr <= 6) ? 1.0f : 0.0f;
        const float m1 = (rr >= 1) ? 1.0f : 0.0f;
#pragma unroll
        for (int jj = 0; jj < 7; jj++) {
            const size_t m = rb + xs[jj];
            ulonglong2 ka = kp[m];
            ulonglong2 kb = kp[LPIX + m];
            ulonglong2 kc = kp[2 * (size_t)LPIX + m];
            ulonglong2 kd = kp[3 * (size_t)LPIX + m];
            u64 s0a = 0ULL, s0b = 0ULL, s1a = 0ULL, s1b = 0ULL;
            ffma2(s0a, q0[0], ka.x); ffma2(s1a, q1[0], ka.x);
            ffma2(s0b, q0[4], kc.x); ffma2(s1b, q1[4], kc.x);
            ffma2(s0a, q0[1], ka.y); ffma2(s1a, q1[1], ka.y);
            ffma2(s0b, q0[5], kc.y); ffma2(s1b, q1[5], kc.y);
            ffma2(s0a, q0[2], kb.x); ffma2(s1a, q1[2], kb.x);
            ffma2(s0b, q0[6], kd.x); ffma2(s1b, q1[6], kd.x);
            ffma2(s0a, q0[3], kb.y); ffma2(s1a, q1[3], kb.y);
            ffma2(s0b, q0[7], kd.y); ffma2(s1b, q1[7], kd.y);
            float2 A0 = unpack2(s0a), B0 = unpack2(s0b);
            float2 A1 = unpack2(s1a), B1 = unpack2(s1b);
            float e0 = __expf(qpec0 + (A0.x + A0.y) + (B0.x + B0.y)) * m0;
            float e1 = __expf(qpec1 + (A1.x + A1.y) + (B1.x + B1.y)) * m1;
            sum0 += e0; sum1 += e1;
            u64 e02 = pack2(e0, e0);
            u64 e12 = pack2(e1, e1);
            ulonglong2 va = vp[m];
            ulonglong2 vb = vp[LPIX + m];
            ulonglong2 vc = vp[2 * (size_t)LPIX + m];
            ulonglong2 vd = vp[3 * (size_t)LPIX + m];
            ffma2(o0[0], e02, va.x); ffma2(o1[0], e12, va.x);
            ffma2(o0[1], e02, va.y); ffma2(o1[1], e12, va.y);
            ffma2(o0[2], e02, vb.x); ffma2(o1[2], e12, vb.x);
            ffma2(o0[3], e02, vb.y); ffma2(o1[3], e12, vb.y);
            ffma2(o0[4], e02, vc.x); ffma2(o1[4], e12, vc.x);
            ffma2(o0[5], e02, vc.y); ffma2(o1[5], e12, vc.y);
            ffma2(o0[6], e02, vd.x); ffma2(o1[6], e12, vd.x);
            ffma2(o0[7], e02, vd.y); ffma2(o1[7], e12, vd.y);
        }
    }

    if (half) {
        s_sum[0][t] = sum0; s_sum[1][t] = sum1;
#pragma unroll
        for (int c = 0; c < 8; c++) {
            float2 a = unpack2(o0[c]);
            s_o[0][t][2*c] = a.x; s_o[0][t][2*c+1] = a.y;
            float2 b = unpack2(o1[c]);
            s_o[1][t][2*c] = b.x; s_o[1][t][2*c+1] = b.y;
        }
    }
    __syncthreads();
    if (!half) {
        const float r1 = rate1[0];
        const float sc0 = r1 / (sum0 + s_sum[0][t]);
        const float sc1 = r1 / (sum1 + s_sum[1][t]);
        size_t ob0 = (size_t)(n * 16) * LPIX + l0;
#pragma unroll
        for (int c = 0; c < 8; c++) {
            float2 a = unpack2(o0[c]);
            float u0 = a.x + s_o[0][t][2*c];
            float u1 = a.y + s_o[0][t][2*c+1];
            float* p0 = out + ob0 + (size_t)(2*c) * LPIX;
            float* p1 = out + ob0 + (size_t)(2*c+1) * LPIX;
            *p0 = fmaf(sc0, u0, *p0);
            *p1 = fmaf(sc0, u1, *p1);
        }
        size_t ob1 = ob0 + 128;
#pragma unroll
        for (int c = 0; c < 8; c++) {
            float2 b = unpack2(o1[c]);
            float u0 = b.x + s_o[1][t][2*c];
            float u1 = b.y + s_o[1][t][2*c+1];
            float* p0 = out + ob1 + (size_t)(2*c) * LPIX;
            float* p1 = out + ob1 + (size_t)(2*c+1) * LPIX;
            *p0 = fmaf(sc1, u0, *p0);
            *p1 = fmaf(sc1, u1, *p1);
        }
    }
}

// ---------------------------------------------------------------------------
extern "C" void kernel_launch(void* const* d_in, const int* in_sizes, int n_in,
                              void* d_out, int out_size)
{
    const float* x     = (const float*)d_in[0];
    const float* w1    = (const float*)d_in[1];
    const float* b1    = (const float*)d_in[2];
    const float* w2    = (const float*)d_in[3];
    const float* b2    = (const float*)d_in[4];
    const float* w3    = (const float*)d_in[5];
    const float* b3    = (const float*)d_in[6];
    const float* wp    = (const float*)d_in[7];
    const float* bp    = (const float*)d_in[8];
    const float* wfc   = (const float*)d_in[9];
    const float* wdep  = (const float*)d_in[10];
    const float* bdep  = (const float*)d_in[11];
    const float* rate1 = (const float*)d_in[12];
    const float* rate2 = (const float*)d_in[13];
    float* out = (float*)d_out;

    cudaFuncSetAttribute(k4_conv, cudaFuncAttributeMaxDynamicSharedMemorySize, 27 * 1024 * 4);

    k0_weff<<<74, 128>>>(w1, b1, w2, b2, w3, b3, wfc);
    fat1<<<dim3(32, 21, 2), 128>>>(x, w1, b1, w2, b2, w3, b3, wp, bp);
    k4_conv<<<dim3(8, 16, 2), 256, 27 * 1024 * 4>>>(wdep, bdep, rate2, out);
    k3_att<<<dim3(32, 8), 256>>>(rate1, out);
}

// round 16
// speedup vs baseline: 1.1055x; 1.1055x over previous
#include <cuda_runtime.h>
#include <cuda_bf16.h>
#include <cstdint>

// Fixed shapes: x=(2,64,8,32,32); HEAD=4, HEAD_DIM=16; H2=64, W2=128; L=8192
#define LPIX 8192
#define NH 8   // b*HEAD

typedef unsigned long long u64;

// Scratch (device globals) — all fp32 float4 planes [n*4+c4][l]
__device__ float4 g_QS4[NH * 4 * LPIX];   // q*0.25
__device__ float4 g_KM4[NH * 4 * LPIX];   // k - pe
__device__ float4 g_VV4[NH * 4 * LPIX];   // v
__device__ float  g_QPEC[NH * LPIX];      // sum_c q_s[c]*pe[c]
__device__ __align__(16) float g_F144[2 * 144 * LPIX]; // planar [b][ch144][l]

// ---- packed f32x2 helpers (sm_103a) ---------------------------------------
__device__ __forceinline__ void ffma2(u64 &d, u64 a, u64 b) {
    asm("fma.rn.f32x2 %0, %1, %2, %0;" : "+l"(d) : "l"(a), "l"(b));
}
__device__ __forceinline__ u64 pack2(float lo, float hi) {
    u64 r; asm("mov.b64 %0, {%1, %2};" : "=l"(r) : "f"(lo), "f"(hi)); return r;
}
__device__ __forceinline__ float2 unpack2(u64 v) {
    float lo, hi; asm("mov.b64 {%0, %1}, %2;" : "=f"(lo), "=f"(hi) : "l"(v)); return make_float2(lo, hi);
}
// PDL: wait for the previous kernel's grid before touching its outputs.
__device__ __forceinline__ void grid_dep_wait() {
    asm volatile("griddepcontrol.wait;" ::: "memory");
}

// ---------------------------------------------------------------------------
// K1: q/k/v 1x1 conv + PE fold.  2-pixel blocking; LDS.64 weight reads
// interleaved with FFMA2.  Block = 128 threads = 256 pixels.
// ---------------------------------------------------------------------------
__global__ __launch_bounds__(128) void k1_qkv(
    const float* __restrict__ x,
    const float* __restrict__ w1, const float* __restrict__ b1,
    const float* __restrict__ w2, const float* __restrict__ b2,
    const float* __restrict__ w3, const float* __restrict__ b3,
    const float* __restrict__ wp, const float* __restrict__ bp)
{
    __shared__ float sw[64][16];
    __shared__ float sb[16], swp[48], sbp[16];
    const int tid = threadIdx.x;
    const int ht = blockIdx.y;
    const int head = ht / 3, type = ht - head * 3;
    const int b = blockIdx.z;

    const float* wm = (type == 0) ? w1 : (type == 1) ? w2 : w3;
    const float* bm = (type == 0) ? b1 : (type == 1) ? b2 : b3;

    for (int i = tid; i < 1024; i += 128) {
        int c = i & 15, cin = i >> 4;
        sw[cin][c] = wm[(head * 16 + c) * 64 + cin];
    }
    if (tid < 16) { sb[tid] = bm[head*16+tid]; sbp[tid] = bp[tid]; }
    if (tid < 48) swp[tid] = wp[tid];
    __syncthreads();

    const int l0 = blockIdx.x * 256 + tid * 2;

    u64 acc[2][8];
#pragma unroll
    for (int j = 0; j < 8; j++) {
        u64 bj = pack2(sb[2*j], sb[2*j+1]);
        acc[0][j] = bj;
        acc[1][j] = bj;
    }

    const float* xp = x + (size_t)b * 64 * LPIX + l0;
#pragma unroll 4
    for (int cin = 0; cin < 64; cin++) {
        float2 xv = *reinterpret_cast<const float2*>(xp + (size_t)cin * LPIX);
        u64 xa = pack2(xv.x, xv.x);
        u64 xb = pack2(xv.y, xv.y);
        const u64* w2p = reinterpret_cast<const u64*>(sw[cin]);
#pragma unroll
        for (int j = 0; j < 8; j++) {
            u64 wj = w2p[j];
            ffma2(acc[0][j], xa, wj);
            ffma2(acc[1][j], xb, wj);
        }
    }

    const int n = b * 4 + head;
#pragma unroll
    for (int p = 0; p < 2; p++) {
        const int l = l0 + p;
        float a[16];
#pragma unroll
        for (int j = 0; j < 8; j++) {
            float2 t = unpack2(acc[p][j]); a[2*j] = t.x; a[2*j+1] = t.y;
        }
        int di = l >> 10, wi = (l >> 5) & 31, hi = l & 31;
        float ldv = di * (2.0f/7.0f)  - 1.0f;
        float lwv = wi * (2.0f/31.0f) - 1.0f;
        float lhv = hi * (2.0f/31.0f) - 1.0f;
        float pe[16];
#pragma unroll
        for (int c = 0; c < 16; c++)
            pe[c] = swp[c*3] * ldv + swp[c*3+1] * lwv + swp[c*3+2] * lhv + sbp[c];

        if (type == 0) {
            float qpec = 0.0f;
#pragma unroll
            for (int c = 0; c < 16; c++) { a[c] *= 0.25f; qpec += a[c] * pe[c]; }
#pragma unroll
            for (int c4 = 0; c4 < 4; c4++)
                g_QS4[((size_t)(n * 4 + c4)) * LPIX + l] =
                    make_float4(a[c4*4], a[c4*4+1], a[c4*4+2], a[c4*4+3]);
            g_QPEC[n * LPIX + l] = qpec;
        } else if (type == 1) {
#pragma unroll
            for (int c = 0; c < 16; c++) a[c] -= pe[c];
#pragma unroll
            for (int c4 = 0; c4 < 4; c4++)
                g_KM4[((size_t)(n * 4 + c4)) * LPIX + l] =
                    make_float4(a[c4*4], a[c4*4+1], a[c4*4+2], a[c4*4+3]);
        } else {
#pragma unroll
            for (int c4 = 0; c4 < 4; c4++)
                g_VV4[((size_t)(n * 4 + c4)) * LPIX + l] =
                    make_float4(a[c4*4], a[c4*4+1], a[c4*4+2], a[c4*4+3]);
        }
    }
}

// ---------------------------------------------------------------------------
// K2: f144 = wfc(9x12) over heads.  Thread per (b, l, c4).
// PDL: stages wfc/wp/bp BEFORE griddepcontrol.wait (they are kernel inputs,
// not k1 outputs), then waits, then reads k1's q/k/v planes.
// ---------------------------------------------------------------------------
__global__ __launch_bounds__(128) void k2_f144(
    const float* __restrict__ wfc,
    const float* __restrict__ wp, const float* __restrict__ bp)
{
    __shared__ float swfc[9][12];
    __shared__ float swp[48], sbp[16];
    int tid = threadIdx.x;
    if (tid < 108) swfc[tid / 12][tid % 12] = wfc[tid];
    if (tid < 48)  swp[tid] = wp[tid];
    if (tid < 16)  sbp[tid] = bp[tid];
    __syncthreads();

    const int c4 = blockIdx.y;
    const int b = blockIdx.z;
    const int l = blockIdx.x * 128 + tid;

    int di = l >> 10, wi = (l >> 5) & 31, hi = l & 31;
    float ldv = di * (2.0f/7.0f)  - 1.0f;
    float lwv = wi * (2.0f/31.0f) - 1.0f;
    float lhv = hi * (2.0f/31.0f) - 1.0f;
    float pe4[4];
#pragma unroll
    for (int c = 0; c < 4; c++) {
        int cc = c4 * 4 + c;
        pe4[c] = swp[cc*3] * ldv + swp[cc*3+1] * lwv + swp[cc*3+2] * lhv + sbp[cc];
    }

    grid_dep_wait();   // k1's q/k/v must be complete from here on

    float qv[4][4], kv[4][4], vv[4][4];
#pragma unroll
    for (int h = 0; h < 4; h++) {
        int n = b * 4 + h;
        size_t idx = ((size_t)(n * 4 + c4)) * LPIX + l;
        float4 q = g_QS4[idx];
        qv[h][0] = q.x*4.0f; qv[h][1] = q.y*4.0f; qv[h][2] = q.z*4.0f; qv[h][3] = q.w*4.0f;
        float4 k = g_KM4[idx];
        kv[h][0] = k.x + pe4[0]; kv[h][1] = k.y + pe4[1];
        kv[h][2] = k.z + pe4[2]; kv[h][3] = k.w + pe4[3];
        float4 v = g_VV4[idx];
        vv[h][0] = v.x; vv[h][1] = v.y; vv[h][2] = v.z; vv[h][3] = v.w;
    }

#pragma unroll
    for (int j = 0; j < 9; j++) {
        float f[4] = {0.f, 0.f, 0.f, 0.f};
#pragma unroll
        for (int h = 0; h < 4; h++) {
            float aq = swfc[j][h], ak = swfc[j][4+h], av = swfc[j][8+h];
#pragma unroll
            for (int c = 0; c < 4; c++)
                f[c] += aq * qv[h][c] + ak * kv[h][c] + av * vv[h][c];
        }
#pragma unroll
        for (int c = 0; c < 4; c++)
            g_F144[((size_t)(b * 144 + j * 16 + c4 * 4 + c)) * LPIX + l] = f[c];
    }
}

// ---------------------------------------------------------------------------
// K4: grouped 3x3 conv from smem-staged F144 rows; 4 pixels per thread.
// PDL: stages wdep weights before griddepcontrol.wait, then reads F144.
// ---------------------------------------------------------------------------
__global__ __launch_bounds__(256) void k4_conv(
    const float* __restrict__ wdep, const float* __restrict__ bdep,
    const float* __restrict__ rate2,
    float* __restrict__ out)
{
    extern __shared__ float sm[];                 // 27 rows x 1024 floats
    __shared__ u64 w01[81], w23[81];
    __shared__ float sb[4];
    __shared__ float sr2;
    const int tid = threadIdx.x;
    const int dd = blockIdx.x, go = blockIdx.y, b = blockIdx.z;

    if (tid < 81) {
        w01[tid] = pack2(wdep[(go*4+0)*81 + tid], wdep[(go*4+1)*81 + tid]);
        w23[tid] = pack2(wdep[(go*4+2)*81 + tid], wdep[(go*4+3)*81 + tid]);
    }
    if (tid < 4) sb[tid] = bdep[go*4+tid];
    if (tid == 0) sr2 = rate2[0];

    grid_dep_wait();   // k2's F144 must be complete from here on

    for (int i = tid; i < 27 * 256; i += 256) {
        int row = i >> 8, px4 = (i & 255) << 2;
        int ci = row / 3, r = row - ci * 3;
        int ddn = dd + r - 1;
        float4 val = make_float4(0.f, 0.f, 0.f, 0.f);
        if ((unsigned)ddn < 8u)
            val = *reinterpret_cast<const float4*>(
                g_F144 + ((size_t)(b*144 + go*9 + ci)) * LPIX + ddn * 1024 + px4);
        *reinterpret_cast<float4*>(&sm[row * 1024 + px4]) = val;
    }
    __syncthreads();

    const int p0 = tid * 4;
    u64 a01[4], a23[4];
#pragma unroll
    for (int p = 0; p < 4; p++) {
        a01[p] = pack2(sb[0], sb[1]);
        a23[p] = pack2(sb[2], sb[3]);
    }

#pragma unroll
    for (int ci = 0; ci < 9; ci++) {
#pragma unroll
        for (int r = 0; r < 3; r++) {
            const float* row = sm + (ci * 3 + r) * 1024;
            float v[6];
            float4 mid = *reinterpret_cast<const float4*>(row + p0);
            v[1] = mid.x; v[2] = mid.y; v[3] = mid.z; v[4] = mid.w;
            v[0] = (p0 > 0)        ? row[p0 - 1] : 0.0f;
            v[5] = (p0 + 4 < 1024) ? row[p0 + 4] : 0.0f;
            int t = ci * 9 + r * 3;
#pragma unroll
            for (int kw = 0; kw < 3; kw++) {
                u64 wa = w01[t + kw], wb = w23[t + kw];
#pragma unroll
                for (int p = 0; p < 4; p++) {
                    u64 vm = pack2(v[p + kw], v[p + kw]);
                    ffma2(a01[p], vm, wa);
                    ffma2(a23[p], vm, wb);
                }
            }
        }
    }

    size_t ob = ((size_t)(b * 64 + go * 4)) * LPIX + dd * 1024 + p0;
    float o0[4], o1[4], o2v[4], o3[4];
#pragma unroll
    for (int p = 0; p < 4; p++) {
        float2 r01 = unpack2(a01[p]), r23 = unpack2(a23[p]);
        o0[p] = sr2 * r01.x; o1[p] = sr2 * r01.y;
        o2v[p] = sr2 * r23.x; o3[p] = sr2 * r23.y;
    }
    *reinterpret_cast<float4*>(out + ob)            = make_float4(o0[0], o0[1], o0[2], o0[3]);
    *reinterpret_cast<float4*>(out + ob + LPIX)     = make_float4(o1[0], o1[1], o1[2], o1[3]);
    *reinterpret_cast<float4*>(out + ob + 2*LPIX)   = make_float4(o2v[0], o2v[1], o2v[2], o2v[3]);
    *reinterpret_cast<float4*>(out + ob + 3*LPIX)   = make_float4(o3[0], o3[1], o3[2], o3[3]);
}

// ---------------------------------------------------------------------------
// K3: 7x7 window attention, fused no-max softmax, fp32, native u64 loads,
// vertical 2-pixel blocking + 2-way row split; 2 blocks/SM.
// PDL: computes reflect tables before griddepcontrol.wait, then reads
// k1's planes and k4's out.
// ---------------------------------------------------------------------------
__global__ __launch_bounds__(256, 2) void k3_att(
    const float* __restrict__ rate1, float* __restrict__ out)
{
    __shared__ float s_sum[2][128];
    __shared__ float s_o[2][128][17];

    const int n = blockIdx.y;
    const int tid = threadIdx.x;
    const int half = tid >> 7;
    const int t = tid & 127;           // x coordinate
    const int y0 = blockIdx.x << 1;
    const int l0 = (y0 << 7) + t;
    const int l1 = l0 + 128;

    const ulonglong2* __restrict__ kp =
        reinterpret_cast<const ulonglong2*>(g_KM4 + (size_t)(n * 4) * LPIX);
    const ulonglong2* __restrict__ vp =
        reinterpret_cast<const ulonglong2*>(g_VV4 + (size_t)(n * 4) * LPIX);
    const ulonglong2* __restrict__ qp =
        reinterpret_cast<const ulonglong2*>(g_QS4 + (size_t)(n * 4) * LPIX);

    int xs[7];
#pragma unroll
    for (int j = 0; j < 7; j++) {
        int xm = t + j - 3;
        xs[j] = xm < 0 ? -xm : (xm > 127 ? 254 - xm : xm);
    }

    grid_dep_wait();   // k1 planes + k4's out must be complete from here on

    u64 q0[8], q1[8];
#pragma unroll
    for (int c4 = 0; c4 < 4; c4++) {
        ulonglong2 qa = qp[(size_t)c4 * LPIX + l0];
        q0[c4*2] = qa.x; q0[c4*2+1] = qa.y;
        ulonglong2 qb = qp[(size_t)c4 * LPIX + l1];
        q1[c4*2] = qb.x; q1[c4*2+1] = qb.y;
    }
    const float qpec0 = g_QPEC[n * LPIX + l0];
    const float qpec1 = g_QPEC[n * LPIX + l1];

    u64 o0[8], o1[8];
#pragma unroll
    for (int c = 0; c < 8; c++) { o0[c] = 0ULL; o1[c] = 0ULL; }
    float sum0 = 0.0f, sum1 = 0.0f;

#pragma unroll 1
    for (int r = 0; r < 4; r++) {
        const int rr = half * 4 + r;             // union row 0..7
        int yy = y0 + rr - 3;
        yy = yy < 0 ? -yy : (yy > 63 ? 126 - yy : yy);
        const int rb = yy << 7;
        const float m0 = (rr <= 6) ? 1.0f : 0.0f;
        const float m1 = (rr >= 1) ? 1.0f : 0.0f;
#pragma unroll
        for (int j = 0; j < 7; j++) {
            const size_t m = rb + xs[j];
            ulonglong2 ka = kp[m];
            ulonglong2 kb = kp[LPIX + m];
            ulonglong2 kc = kp[2 * (size_t)LPIX + m];
            ulonglong2 kd = kp[3 * (size_t)LPIX + m];
            u64 s0a = 0ULL, s0b = 0ULL, s1a = 0ULL, s1b = 0ULL;
            ffma2(s0a, q0[0], ka.x); ffma2(s1a, q1[0], ka.x);
            ffma2(s0b, q0[4], kc.x); ffma2(s1b, q1[4], kc.x);
            ffma2(s0a, q0[1], ka.y); ffma2(s1a, q1[1], ka.y);
            ffma2(s0b, q0[5], kc.y); ffma2(s1b, q1[5], kc.y);
            ffma2(s0a, q0[2], kb.x); ffma2(s1a, q1[2], kb.x);
            ffma2(s0b, q0[6], kd.x); ffma2(s1b, q1[6], kd.x);
            ffma2(s0a, q0[3], kb.y); ffma2(s1a, q1[3], kb.y);
            ffma2(s0b, q0[7], kd.y); ffma2(s1b, q1[7], kd.y);
            float2 A0 = unpack2(s0a), B0 = unpack2(s0b);
            float2 A1 = unpack2(s1a), B1 = unpack2(s1b);
            float e0 = __expf(qpec0 + (A0.x + A0.y) + (B0.x + B0.y)) * m0;
            float e1 = __expf(qpec1 + (A1.x + A1.y) + (B1.x + B1.y)) * m1;
            sum0 += e0; sum1 += e1;
            u64 e02 = pack2(e0, e0);
            u64 e12 = pack2(e1, e1);
            ulonglong2 va = vp[m];
            ulonglong2 vb = vp[LPIX + m];
            ulonglong2 vc = vp[2 * (size_t)LPIX + m];
            ulonglong2 vd = vp[3 * (size_t)LPIX + m];
            ffma2(o0[0], e02, va.x); ffma2(o1[0], e12, va.x);
            ffma2(o0[1], e02, va.y); ffma2(o1[1], e12, va.y);
            ffma2(o0[2], e02, vb.x); ffma2(o1[2], e12, vb.x);
            ffma2(o0[3], e02, vb.y); ffma2(o1[3], e12, vb.y);
            ffma2(o0[4], e02, vc.x); ffma2(o1[4], e12, vc.x);
            ffma2(o0[5], e02, vc.y); ffma2(o1[5], e12, vc.y);
            ffma2(o0[6], e02, vd.x); ffma2(o1[6], e12, vd.x);
            ffma2(o0[7], e02, vd.y); ffma2(o1[7], e12, vd.y);
        }
    }

    if (half) {
        s_sum[0][t] = sum0; s_sum[1][t] = sum1;
#pragma unroll
        for (int c = 0; c < 8; c++) {
            float2 a = unpack2(o0[c]);
            s_o[0][t][2*c] = a.x; s_o[0][t][2*c+1] = a.y;
            float2 b = unpack2(o1[c]);
            s_o[1][t][2*c] = b.x; s_o[1][t][2*c+1] = b.y;
        }
    }
    __syncthreads();
    if (!half) {
        const float r1 = rate1[0];
        const float sc0 = r1 / (sum0 + s_sum[0][t]);
        const float sc1 = r1 / (sum1 + s_sum[1][t]);
        size_t ob0 = (size_t)(n * 16) * LPIX + l0;
#pragma unroll
        for (int c = 0; c < 8; c++) {
            float2 a = unpack2(o0[c]);
            float u0 = a.x + s_o[0][t][2*c];
            float u1 = a.y + s_o[0][t][2*c+1];
            float* p0 = out + ob0 + (size_t)(2*c) * LPIX;
            float* p1 = out + ob0 + (size_t)(2*c+1) * LPIX;
            *p0 = fmaf(sc0, u0, *p0);
            *p1 = fmaf(sc0, u1, *p1);
        }
        size_t ob1 = ob0 + 128;
#pragma unroll
        for (int c = 0; c < 8; c++) {
            float2 b = unpack2(o1[c]);
            float u0 = b.x + s_o[1][t][2*c];
            float u1 = b.y + s_o[1][t][2*c+1];
            float* p0 = out + ob1 + (size_t)(2*c) * LPIX;
            float* p1 = out + ob1 + (size_t)(2*c+1) * LPIX;
            *p0 = fmaf(sc1, u0, *p0);
            *p1 = fmaf(sc1, u1, *p1);
        }
    }
}

// ---------------------------------------------------------------------------
extern "C" void kernel_launch(void* const* d_in, const int* in_sizes, int n_in,
                              void* d_out, int out_size)
{
    const float* x     = (const float*)d_in[0];
    const float* w1    = (const float*)d_in[1];
    const float* b1    = (const float*)d_in[2];
    const float* w2    = (const float*)d_in[3];
    const float* b2    = (const float*)d_in[4];
    const float* w3    = (const float*)d_in[5];
    const float* b3    = (const float*)d_in[6];
    const float* wp    = (const float*)d_in[7];
    const float* bp    = (const float*)d_in[8];
    const float* wfc   = (const float*)d_in[9];
    const float* wdep  = (const float*)d_in[10];
    const float* bdep  = (const float*)d_in[11];
    const float* rate1 = (const float*)d_in[12];
    const float* rate2 = (const float*)d_in[13];
    float* out = (float*)d_out;

    cudaFuncSetAttribute(k4_conv, cudaFuncAttributeMaxDynamicSharedMemorySize, 27 * 1024 * 4);

    // k1: plain launch
    k1_qkv<<<dim3(32, 12, 2), 128>>>(x, w1, b1, w2, b2, w3, b3, wp, bp);

    // k2/k4/k3: programmatic dependent launch — prologue overlaps predecessor tail
    cudaLaunchAttribute attrs[1];
    attrs[0].id = cudaLaunchAttributeProgrammaticStreamSerialization;
    attrs[0].val.programmaticStreamSerializationAllowed = 1;

    {
        cudaLaunchConfig_t cfg = {};
        cfg.gridDim = dim3(64, 4, 2);
        cfg.blockDim = dim3(128, 1, 1);
        cfg.attrs = attrs; cfg.numAttrs = 1;
        cudaLaunchKernelEx(&cfg, k2_f144, wfc, wp, bp);
    }
    {
        cudaLaunchConfig_t cfg = {};
        cfg.gridDim = dim3(8, 16, 2);
        cfg.blockDim = dim3(256, 1, 1);
        cfg.dynamicSmemBytes = 27 * 1024 * 4;
        cfg.attrs = attrs; cfg.numAttrs = 1;
        cudaLaunchKernelEx(&cfg, k4_conv, wdep, bdep, rate2, out);
    }
    {
        cudaLaunchConfig_t cfg = {};
        cfg.gridDim = dim3(32, 8, 1);
        cfg.blockDim = dim3(256, 1, 1);
        cfg.attrs = attrs; cfg.numAttrs = 1;
        cudaLaunchKernelEx(&cfg, k3_att, rate1, out);
    }
}